// round 6
// baseline (speedup 1.0000x reference)
#include <cuda_runtime.h>
#include <cuda_bf16.h>
#include <cmath>

#define N_NODES 20000
#define N_EDGES 320000
#define MAXD    1024

// ---------------- scratch (static __device__, no allocs) ----------------
__device__ float g_bufA[(size_t)N_NODES * MAXD];   // ping (layer outputs)
__device__ float g_bufB[(size_t)N_NODES * MAXD];   // pong
__device__ float g_Z   [(size_t)N_NODES * MAXD];   // aggregated input (din space)
__device__ float g_el[N_NODES];
__device__ float g_er[N_NODES];
__device__ float g_wal[512];
__device__ float g_war[512];
__device__ float g_alpha[N_EDGES];
__device__ int   g_rowptr[N_NODES + 1];
__device__ int   g_cnt[N_NODES];
__device__ int   g_fill[N_NODES];
__device__ int   g_csrc[N_EDGES];
__device__ float g_pool[MAXD];

// ---------------- CSR build ----------------
__global__ void zero_kernel() {
    int i = blockIdx.x * blockDim.x + threadIdx.x;
    if (i < N_NODES) { g_cnt[i] = 0; g_fill[i] = 0; }
}

__global__ void count_kernel(const int* __restrict__ dst) {
    int e = blockIdx.x * blockDim.x + threadIdx.x;
    if (e < N_EDGES) atomicAdd(&g_cnt[dst[e]], 1);
}

__global__ void scan_kernel() {
    __shared__ int sd[1024];
    __shared__ int carry;
    if (threadIdx.x == 0) carry = 0;
    __syncthreads();
    for (int base = 0; base < N_NODES; base += 1024) {
        int i = base + threadIdx.x;
        int v = (i < N_NODES) ? g_cnt[i] : 0;
        sd[threadIdx.x] = v;
        __syncthreads();
        for (int off = 1; off < 1024; off <<= 1) {
            int t = (threadIdx.x >= off) ? sd[threadIdx.x - off] : 0;
            __syncthreads();
            sd[threadIdx.x] += t;
            __syncthreads();
        }
        if (i < N_NODES) g_rowptr[i] = carry + sd[threadIdx.x] - v;
        __syncthreads();
        if (threadIdx.x == 0) carry += sd[1023];
        __syncthreads();
    }
    if (threadIdx.x == 0) g_rowptr[N_NODES] = carry;
}

__global__ void fill_kernel(const int* __restrict__ src, const int* __restrict__ dst) {
    int e = blockIdx.x * blockDim.x + threadIdx.x;
    if (e < N_EDGES) {
        int d = dst[e];
        int p = atomicAdd(&g_fill[d], 1);
        g_csrc[g_rowptr[d] + p] = src[e];
    }
}

// ---------------- W@al, W@ar projection vectors (warp per din-row) ----------------
__global__ void wv_kernel(const float* __restrict__ W,
                          const float* __restrict__ al,
                          const float* __restrict__ ar, int din, int dout)
{
    int g = blockIdx.x * blockDim.x + threadIdx.x;
    int i = g >> 5, lane = g & 31;
    if (i >= din) return;
    const float* row = W + (size_t)i * dout;
    float sl = 0.f, sr = 0.f;
    for (int j = lane; j < dout; j += 32) {
        float w = row[j];
        sl += w * al[j];
        sr += w * ar[j];
    }
#pragma unroll
    for (int o = 16; o > 0; o >>= 1) {
        sl += __shfl_down_sync(0xffffffffu, sl, o);
        sr += __shfl_down_sync(0xffffffffu, sr, o);
    }
    if (lane == 0) { g_wal[i] = sl; g_war[i] = sr; }
}

// ---------------- per-node el / er from x directly (warp per node) ----------------
__global__ void elr_kernel(const float* __restrict__ X, int din)
{
    int g = blockIdx.x * blockDim.x + threadIdx.x;
    int node = g >> 5, lane = g & 31;
    if (node >= N_NODES) return;
    const float* row = X + (size_t)node * din;
    float sl = 0.f, sr = 0.f;
    for (int c = lane; c < din; c += 32) {
        float v = row[c];
        sl += v * g_wal[c];
        sr += v * g_war[c];
    }
#pragma unroll
    for (int o = 16; o > 0; o >>= 1) {
        sl += __shfl_down_sync(0xffffffffu, sl, o);
        sr += __shfl_down_sync(0xffffffffu, sr, o);
    }
    if (lane == 0) { g_el[node] = sl; g_er[node] = sr; }
}

// ---------------- normalized edge softmax weights (warp per dst node) ----------------
__global__ void alpha_kernel()
{
    int g = blockIdx.x * blockDim.x + threadIdx.x;
    int node = g >> 5, lane = g & 31;
    if (node >= N_NODES) return;
    int beg = g_rowptr[node], end = g_rowptr[node + 1];
    if (beg == end) return;
    float er_n = g_er[node];

    float m = -INFINITY;
    for (int i = beg + lane; i < end; i += 32) {
        float x = g_el[g_csrc[i]] + er_n;
        x = x > 0.f ? x : 0.2f * x;
        m = fmaxf(m, x);
    }
#pragma unroll
    for (int o = 16; o > 0; o >>= 1)
        m = fmaxf(m, __shfl_xor_sync(0xffffffffu, m, o));

    float s = 0.f;
    for (int i = beg + lane; i < end; i += 32) {
        float x = g_el[g_csrc[i]] + er_n;
        x = x > 0.f ? x : 0.2f * x;
        float w = __expf(x - m);
        g_alpha[i] = w;
        s += w;
    }
#pragma unroll
    for (int o = 16; o > 0; o >>= 1)
        s += __shfl_xor_sync(0xffffffffu, s, o);

    float inv = 1.f / s;
    for (int i = beg + lane; i < end; i += 32)
        g_alpha[i] *= inv;
}

// ---------------- weighted gather in din space: Z[n] = sum alpha * X[src] ----------------
template <int BS>
__global__ __launch_bounds__(BS) void gather_kernel(
    const float* __restrict__ X, float* __restrict__ Z, int din)
{
    int n   = blockIdx.x;
    int c   = blockIdx.y * BS + threadIdx.x;
    int tid = threadIdx.x;
    int beg = g_rowptr[n], end = g_rowptr[n + 1];

    __shared__ int   s_s[256];
    __shared__ float s_w[256];

    float acc = 0.f;
    for (int base = beg; base < end; base += 256) {
        int cnt = min(256, end - base);
        for (int i = tid; i < cnt; i += BS) {
            s_s[i] = g_csrc[base + i];
            s_w[i] = g_alpha[base + i];
        }
        __syncthreads();
#pragma unroll 4
        for (int q = 0; q < cnt; q++)
            acc += s_w[q] * X[(size_t)s_s[q] * din + c];
        __syncthreads();
    }
    Z[(size_t)n * din + c] = acc;
}

// ---------------- tf32 tensor-core GEMM + fused bias/tanh epilogue ----------------
// Y[M,N] = tanh(Z[M,K] @ W[K,N] + b[N])
#define GBM 128
#define GBN 128
#define GBK 16
#define AST (GBK + 4)
#define BST (GBN + 8)

__device__ __forceinline__ unsigned f2tf32(float f) {
    unsigned u;
    asm("cvt.rna.tf32.f32 %0, %1;" : "=r"(u) : "f"(f));
    return u;
}

__device__ __forceinline__ void cp_async16(void* smem_dst, const void* gsrc) {
    unsigned s = (unsigned)__cvta_generic_to_shared(smem_dst);
    asm volatile("cp.async.cg.shared.global [%0], [%1], 16;\n" :: "r"(s), "l"(gsrc));
}

__global__ __launch_bounds__(256) void gemm_tf32_kernel(
    const float* __restrict__ A, const float* __restrict__ B,
    const float* __restrict__ bias, float* __restrict__ C,
    int M, int K, int N)
{
    __shared__ __align__(16) float As[2][GBM][AST];
    __shared__ __align__(16) float Bs[2][GBK][BST];

    int tid  = threadIdx.x;
    int lane = tid & 31;
    int warp = tid >> 5;
    int wm = (warp >> 2) * 64;
    int wn = (warp & 3) * 32;
    int g = lane >> 2;
    int t = lane & 3;

    int row0 = blockIdx.y * GBM;
    int col0 = blockIdx.x * GBN;

    float acc[4][4][4];
#pragma unroll
    for (int mi = 0; mi < 4; mi++)
#pragma unroll
        for (int ni = 0; ni < 4; ni++)
#pragma unroll
            for (int r = 0; r < 4; r++) acc[mi][ni][r] = 0.f;

    int nk = K / GBK;

    auto load_stage = [&](int it, int buf) {
#pragma unroll
        for (int i = 0; i < 2; i++) {
            int c = tid + i * 256;
            int m  = c >> 2;
            int kq = c & 3;
            int gm = row0 + m;
            if (gm >= M) gm = M - 1;
            cp_async16(&As[buf][m][kq * 4],
                       A + (size_t)gm * K + it * GBK + kq * 4);
        }
#pragma unroll
        for (int i = 0; i < 2; i++) {
            int c = tid + i * 256;
            int r  = c >> 5;
            int c4 = c & 31;
            cp_async16(&Bs[buf][r][c4 * 4],
                       B + (size_t)(it * GBK + r) * N + col0 + c4 * 4);
        }
        asm volatile("cp.async.commit_group;\n" ::: "memory");
    };

    load_stage(0, 0);

    for (int it = 0; it < nk; it++) {
        int cur = it & 1;
        if (it + 1 < nk) {
            load_stage(it + 1, cur ^ 1);
            asm volatile("cp.async.wait_group 1;\n" ::: "memory");
        } else {
            asm volatile("cp.async.wait_group 0;\n" ::: "memory");
        }
        __syncthreads();

#pragma unroll
        for (int ks = 0; ks < 2; ks++) {
            unsigned a[4][4], b[4][2];
#pragma unroll
            for (int mi = 0; mi < 4; mi++) {
                int rb = wm + mi * 16;
                a[mi][0] = f2tf32(As[cur][rb + g    ][ks * 8 + t    ]);
                a[mi][1] = f2tf32(As[cur][rb + g + 8][ks * 8 + t    ]);
                a[mi][2] = f2tf32(As[cur][rb + g    ][ks * 8 + t + 4]);
                a[mi][3] = f2tf32(As[cur][rb + g + 8][ks * 8 + t + 4]);
            }
#pragma unroll
            for (int ni = 0; ni < 4; ni++) {
                int cb = wn + ni * 8 + g;
                b[ni][0] = f2tf32(Bs[cur][ks * 8 + t    ][cb]);
                b[ni][1] = f2tf32(Bs[cur][ks * 8 + t + 4][cb]);
            }
#pragma unroll
            for (int mi = 0; mi < 4; mi++)
#pragma unroll
                for (int ni = 0; ni < 4; ni++) {
                    asm volatile(
                        "mma.sync.aligned.m16n8k8.row.col.f32.tf32.tf32.f32 "
                        "{%0,%1,%2,%3}, {%4,%5,%6,%7}, {%8,%9}, {%0,%1,%2,%3};\n"
                        : "+f"(acc[mi][ni][0]), "+f"(acc[mi][ni][1]),
                          "+f"(acc[mi][ni][2]), "+f"(acc[mi][ni][3])
                        : "r"(a[mi][0]), "r"(a[mi][1]), "r"(a[mi][2]), "r"(a[mi][3]),
                          "r"(b[ni][0]), "r"(b[ni][1]));
                }
        }
        __syncthreads();
    }

    // ---- fused epilogue: tanh(acc + bias) ----
#pragma unroll
    for (int mi = 0; mi < 4; mi++) {
        int r0 = row0 + wm + mi * 16 + g;
        int r1 = r0 + 8;
#pragma unroll
        for (int ni = 0; ni < 4; ni++) {
            int cc = col0 + wn + ni * 8 + 2 * t;
            float b0 = bias[cc], b1 = bias[cc + 1];
            if (r0 < M) {
                C[(size_t)r0 * N + cc]     = tanhf(acc[mi][ni][0] + b0);
                C[(size_t)r0 * N + cc + 1] = tanhf(acc[mi][ni][1] + b1);
            }
            if (r1 < M) {
                C[(size_t)r1 * N + cc]     = tanhf(acc[mi][ni][2] + b0);
                C[(size_t)r1 * N + cc + 1] = tanhf(acc[mi][ni][3] + b1);
            }
        }
    }
}

// ---------------- readout ----------------
__global__ void pool_kernel(const float* __restrict__ Y, const int* __restrict__ order) {
    int c = blockIdx.x * blockDim.x + threadIdx.x;   // 0..1023
    int rows = order[0] + 1;
    float s = 0.f;
    for (int r = 0; r < rows; r++) s += Y[(size_t)r * MAXD + c];
    g_pool[c] = s / (float)rows;
}

__global__ void logits_kernel(const float* __restrict__ relW,
                              const float* __restrict__ relB,
                              const int* __restrict__ rel,
                              float* __restrict__ out)
{
    int t = threadIdx.x;   // 64 threads
    float s = relB[t];
    for (int k = 0; k < MAXD; k++) s += g_pool[k] * relW[k * 64 + t];
    __shared__ float lg[64];
    lg[t] = s;
    __syncthreads();
    if (t == 0) {
        int idx[64];
        int cnt = 0;
        for (int i = 0; i < 64; i++)
            if (rel[i] != 0) idx[cnt++] = i;
        for (int k = cnt; k < 64; k++) idx[k] = 0;   // jnp.nonzero pad fill=0
        for (int k = 0; k < 64; k++) out[k] = lg[idx[k]];
    }
}

// ---------------- launch ----------------
extern "C" void kernel_launch(void* const* d_in, const int* in_sizes, int n_in,
                              void* d_out, int out_size)
{
    const float* feat  = (const float*)d_in[0];
    const float* W[4]  = {(const float*)d_in[1], (const float*)d_in[5],
                          (const float*)d_in[9], (const float*)d_in[13]};
    const float* al[4] = {(const float*)d_in[2], (const float*)d_in[6],
                          (const float*)d_in[10], (const float*)d_in[14]};
    const float* ar[4] = {(const float*)d_in[3], (const float*)d_in[7],
                          (const float*)d_in[11], (const float*)d_in[15]};
    const float* bb[4] = {(const float*)d_in[4], (const float*)d_in[8],
                          (const float*)d_in[12], (const float*)d_in[16]};
    const float* relW  = (const float*)d_in[17];
    const float* relB  = (const float*)d_in[18];
    const int*   src   = (const int*)d_in[19];
    const int*   dst   = (const int*)d_in[20];
    const int*   rel   = (const int*)d_in[21];
    const int*   order = (const int*)d_in[22];
    float* out = (float*)d_out;

    float *pA, *pB, *pZ;
    cudaGetSymbolAddress((void**)&pA, g_bufA);
    cudaGetSymbolAddress((void**)&pB, g_bufB);
    cudaGetSymbolAddress((void**)&pZ, g_Z);

    // CSR (by dst) — rebuilt every launch, deterministic work
    zero_kernel <<<(N_NODES + 255) / 256, 256>>>();
    count_kernel<<<(N_EDGES + 255) / 256, 256>>>(dst);
    scan_kernel <<<1, 1024>>>();
    fill_kernel <<<(N_EDGES + 255) / 256, 256>>>(src, dst);

    const int din_a [4] = {64, 128, 256, 512};
    const int dout_a[4] = {128, 256, 512, 1024};

    const float* x = feat;
    float* outbufs[4] = {pA, pB, pA, pB};

    for (int l = 0; l < 4; l++) {
        int din = din_a[l], dout = dout_a[l];

        // projection vectors wal = W@al, war = W@ar
        wv_kernel<<<(din * 32 + 255) / 256, 256>>>(W[l], al[l], ar[l], din, dout);

        // el/er directly from x
        elr_kernel<<<(N_NODES * 32 + 255) / 256, 256>>>(x, din);

        // normalized per-edge softmax weights
        alpha_kernel<<<(N_NODES * 32 + 255) / 256, 256>>>();

        // weighted gather in din space: Z = sum alpha * x[src]
        if (din == 64) {
            dim3 gg(N_NODES, 1);
            gather_kernel<64><<<gg, 64>>>(x, pZ, din);
        } else {
            dim3 gg(N_NODES, din / 128);
            gather_kernel<128><<<gg, 128>>>(x, pZ, din);
        }

        // Y = tanh(Z @ W + b)
        float* y = outbufs[l];
        dim3 grid(dout / GBN, (N_NODES + GBM - 1) / GBM);
        gemm_tf32_kernel<<<grid, 256>>>(pZ, W[l], bb[l], y, N_NODES, din, dout);

        x = y;
    }

    pool_kernel<<<MAXD / 256, 256>>>(pB, order);
    logits_kernel<<<1, 64>>>(relW, relB, rel, out);
}

// round 7
// speedup vs baseline: 1.4686x; 1.4686x over previous
#include <cuda_runtime.h>
#include <cuda_bf16.h>
#include <cmath>

#define N_NODES 20000
#define N_EDGES 320000
#define MAXD    1024

// ---------------- scratch (static __device__, no allocs) ----------------
__device__ float g_bufA[(size_t)N_NODES * MAXD];
__device__ float g_bufB[(size_t)N_NODES * MAXD];
__device__ float g_Z   [(size_t)N_NODES * 512];     // aggregated input (din<=512), tf32-rounded
__device__ float g_Wt  [(size_t)512 * 1024];        // tf32-rounded weights (current layer)
__device__ float g_el[N_NODES];
__device__ float g_er[N_NODES];
__device__ float g_wal[512];
__device__ float g_war[512];
__device__ float g_alpha[N_EDGES];
__device__ int   g_rowptr[N_NODES + 1];
__device__ int   g_cnt[N_NODES];
__device__ int   g_fill[N_NODES];
__device__ int   g_csrc[N_EDGES];
__device__ float g_pool[MAXD];

__device__ __forceinline__ unsigned f2tf32(float f) {
    unsigned u;
    asm("cvt.rna.tf32.f32 %0, %1;" : "=r"(u) : "f"(f));
    return u;
}

// ---------------- CSR build ----------------
__global__ void zero_kernel() {
    int i = blockIdx.x * blockDim.x + threadIdx.x;
    if (i < N_NODES) { g_cnt[i] = 0; g_fill[i] = 0; }
}
__global__ void count_kernel(const int* __restrict__ dst) {
    int e = blockIdx.x * blockDim.x + threadIdx.x;
    if (e < N_EDGES) atomicAdd(&g_cnt[dst[e]], 1);
}
__global__ void scan_kernel() {
    __shared__ int sd[1024];
    __shared__ int carry;
    if (threadIdx.x == 0) carry = 0;
    __syncthreads();
    for (int base = 0; base < N_NODES; base += 1024) {
        int i = base + threadIdx.x;
        int v = (i < N_NODES) ? g_cnt[i] : 0;
        sd[threadIdx.x] = v;
        __syncthreads();
        for (int off = 1; off < 1024; off <<= 1) {
            int t = (threadIdx.x >= off) ? sd[threadIdx.x - off] : 0;
            __syncthreads();
            sd[threadIdx.x] += t;
            __syncthreads();
        }
        if (i < N_NODES) g_rowptr[i] = carry + sd[threadIdx.x] - v;
        __syncthreads();
        if (threadIdx.x == 0) carry += sd[1023];
        __syncthreads();
    }
    if (threadIdx.x == 0) g_rowptr[N_NODES] = carry;
}
__global__ void fill_kernel(const int* __restrict__ src, const int* __restrict__ dst) {
    int e = blockIdx.x * blockDim.x + threadIdx.x;
    if (e < N_EDGES) {
        int d = dst[e];
        int p = atomicAdd(&g_fill[d], 1);
        g_csrc[g_rowptr[d] + p] = src[e];
    }
}

// ---------------- projection vectors wal = W@al, war = W@ar ----------------
__global__ void wv_kernel(const float* __restrict__ W,
                          const float* __restrict__ al,
                          const float* __restrict__ ar, int din, int dout)
{
    int g = blockIdx.x * blockDim.x + threadIdx.x;
    int i = g >> 5, lane = g & 31;
    if (i >= din) return;
    const float* row = W + (size_t)i * dout;
    float sl = 0.f, sr = 0.f;
    for (int j = lane; j < dout; j += 32) {
        float w = row[j];
        sl += w * al[j];
        sr += w * ar[j];
    }
#pragma unroll
    for (int o = 16; o > 0; o >>= 1) {
        sl += __shfl_down_sync(0xffffffffu, sl, o);
        sr += __shfl_down_sync(0xffffffffu, sr, o);
    }
    if (lane == 0) { g_wal[i] = sl; g_war[i] = sr; }
}

// ---------------- per-node el / er ----------------
__global__ void elr_kernel(const float* __restrict__ X, int din)
{
    int g = blockIdx.x * blockDim.x + threadIdx.x;
    int node = g >> 5, lane = g & 31;
    if (node >= N_NODES) return;
    const float* row = X + (size_t)node * din;
    float sl = 0.f, sr = 0.f;
    for (int c = lane; c < din; c += 32) {
        float v = row[c];
        sl += v * g_wal[c];
        sr += v * g_war[c];
    }
#pragma unroll
    for (int o = 16; o > 0; o >>= 1) {
        sl += __shfl_down_sync(0xffffffffu, sl, o);
        sr += __shfl_down_sync(0xffffffffu, sr, o);
    }
    if (lane == 0) { g_el[node] = sl; g_er[node] = sr; }
}

// ---------------- normalized edge softmax weights (warp per dst) ----------------
__global__ void alpha_kernel()
{
    int g = blockIdx.x * blockDim.x + threadIdx.x;
    int node = g >> 5, lane = g & 31;
    if (node >= N_NODES) return;
    int beg = g_rowptr[node], end = g_rowptr[node + 1];
    int dg = end - beg;
    if (dg == 0) return;
    float er_n = g_er[node];

    if (dg <= 32) {
        // single-pass register path (common: avg degree 16)
        float x = -INFINITY;
        if (lane < dg) {
            x = g_el[g_csrc[beg + lane]] + er_n;
            x = x > 0.f ? x : 0.2f * x;
        }
        float m = x;
#pragma unroll
        for (int o = 16; o > 0; o >>= 1)
            m = fmaxf(m, __shfl_xor_sync(0xffffffffu, m, o));
        float w = (lane < dg) ? __expf(x - m) : 0.f;
        float s = w;
#pragma unroll
        for (int o = 16; o > 0; o >>= 1)
            s += __shfl_xor_sync(0xffffffffu, s, o);
        if (lane < dg) g_alpha[beg + lane] = w / s;
        return;
    }

    float m = -INFINITY;
    for (int i = beg + lane; i < end; i += 32) {
        float x = g_el[g_csrc[i]] + er_n;
        x = x > 0.f ? x : 0.2f * x;
        m = fmaxf(m, x);
    }
#pragma unroll
    for (int o = 16; o > 0; o >>= 1)
        m = fmaxf(m, __shfl_xor_sync(0xffffffffu, m, o));
    float s = 0.f;
    for (int i = beg + lane; i < end; i += 32) {
        float x = g_el[g_csrc[i]] + er_n;
        x = x > 0.f ? x : 0.2f * x;
        float w = __expf(x - m);
        g_alpha[i] = w;
        s += w;
    }
#pragma unroll
    for (int o = 16; o > 0; o >>= 1)
        s += __shfl_xor_sync(0xffffffffu, s, o);
    float inv = 1.f / s;
    for (int i = beg + lane; i < end; i += 32)
        g_alpha[i] *= inv;
}

// ---------------- weighted gather: warp per (node, 64-channel chunk) ----------------
// Z[n][c] = sum_e alpha_e * X[src_e][c], output tf32-rounded for the GEMM A side.
__global__ __launch_bounds__(256) void gather_kernel(
    const float* __restrict__ X, float* __restrict__ Z, int din, int log2c)
{
    int wg   = (blockIdx.x * blockDim.x + threadIdx.x) >> 5;
    int lane = threadIdx.x & 31;
    int node  = wg >> log2c;
    int chunk = wg & ((1 << log2c) - 1);
    if (node >= N_NODES) return;
    int c0 = chunk * 64 + lane;
    int beg = g_rowptr[node], end = g_rowptr[node + 1];

    const float* Xc = X + c0;
    float acc0 = 0.f, acc1 = 0.f;
    for (int base = beg; base < end; base += 32) {
        int n_e = min(32, end - base);
        int s = 0; float w = 0.f;
        if (lane < n_e) {
            s = g_csrc[base + lane];
            w = g_alpha[base + lane];
        }
#pragma unroll 4
        for (int j = 0; j < n_e; j++) {
            int   sj = __shfl_sync(0xffffffffu, s, j);
            float wj = __shfl_sync(0xffffffffu, w, j);
            const float* row = Xc + (size_t)sj * din;
            acc0 += wj * row[0];
            acc1 += wj * row[32];
        }
    }
    Z[(size_t)node * din + c0]      = __uint_as_float(f2tf32(acc0));
    Z[(size_t)node * din + c0 + 32] = __uint_as_float(f2tf32(acc1));
}

// ---------------- round W to tf32 ----------------
__global__ void round_kernel(const float* __restrict__ W, float* __restrict__ Wt, int n) {
    int i = blockIdx.x * blockDim.x + threadIdx.x;
    if (i < n) Wt[i] = __uint_as_float(f2tf32(W[i]));
}

// ---------------- tf32 GEMM, 3-stage cp.async, fused bias+tanh ----------------
// Y[M,N] = tanh(Z[M,K] @ W[K,N] + b[N]); Z, W already tf32-rounded.
#define GBM 128
#define GBN 128
#define GBK 16
#define AST 20
#define BST 132
#define A_STAGE (GBM * AST)   // 2560 floats
#define B_STAGE (GBK * BST)   // 2112 floats
#define GEMM_SMEM ((3 * (A_STAGE + B_STAGE)) * 4)   // 56064 bytes

__device__ __forceinline__ void cp_async16(void* smem_dst, const void* gsrc) {
    unsigned s = (unsigned)__cvta_generic_to_shared(smem_dst);
    asm volatile("cp.async.cg.shared.global [%0], [%1], 16;\n" :: "r"(s), "l"(gsrc));
}

__global__ __launch_bounds__(256, 2) void gemm_tf32_kernel(
    const float* __restrict__ A, const float* __restrict__ B,
    const float* __restrict__ bias, float* __restrict__ C,
    int M, int K, int N)
{
    extern __shared__ float smbuf[];
    float* Asm = smbuf;                 // [3][GBM][AST]
    float* Bsm = smbuf + 3 * A_STAGE;   // [3][GBK][BST]

    int tid  = threadIdx.x;
    int lane = tid & 31;
    int warp = tid >> 5;
    int wm = (warp >> 2) * 64;
    int wn = (warp & 3) * 32;
    int g = lane >> 2;
    int t = lane & 3;

    int row0 = blockIdx.y * GBM;
    int col0 = blockIdx.x * GBN;

    float acc[4][4][4];
#pragma unroll
    for (int mi = 0; mi < 4; mi++)
#pragma unroll
        for (int ni = 0; ni < 4; ni++)
#pragma unroll
            for (int r = 0; r < 4; r++) acc[mi][ni][r] = 0.f;

    int nk = K / GBK;   // >= 4 for all layers

    auto load_stage = [&](int it) {
        int buf = it % 3;
        float* Ab = Asm + buf * A_STAGE;
        float* Bb = Bsm + buf * B_STAGE;
#pragma unroll
        for (int i = 0; i < 2; i++) {
            int c = tid + i * 256;
            int m  = c >> 2;
            int kq = c & 3;
            int gm = row0 + m;
            if (gm >= M) gm = M - 1;
            cp_async16(Ab + m * AST + kq * 4,
                       A + (size_t)gm * K + it * GBK + kq * 4);
        }
#pragma unroll
        for (int i = 0; i < 2; i++) {
            int c = tid + i * 256;
            int r  = c >> 5;
            int c4 = c & 31;
            cp_async16(Bb + r * BST + c4 * 4,
                       B + (size_t)(it * GBK + r) * N + col0 + c4 * 4);
        }
        asm volatile("cp.async.commit_group;\n" ::: "memory");
    };

    load_stage(0);
    load_stage(1);

    for (int it = 0; it < nk; it++) {
        int cur = it % 3;
        if (it + 1 < nk) {
            asm volatile("cp.async.wait_group 1;\n" ::: "memory");
        } else {
            asm volatile("cp.async.wait_group 0;\n" ::: "memory");
        }
        __syncthreads();
        if (it + 2 < nk) load_stage(it + 2);   // writes buf (it+2)%3 == (it-1)%3, safe after barrier

        float* Ab = Asm + cur * A_STAGE;
        float* Bb = Bsm + cur * B_STAGE;
#pragma unroll
        for (int ks = 0; ks < 2; ks++) {
            unsigned a[4][4], b[4][2];
#pragma unroll
            for (int mi = 0; mi < 4; mi++) {
                int rb = wm + mi * 16;
                a[mi][0] = __float_as_uint(Ab[(rb + g    ) * AST + ks * 8 + t    ]);
                a[mi][1] = __float_as_uint(Ab[(rb + g + 8) * AST + ks * 8 + t    ]);
                a[mi][2] = __float_as_uint(Ab[(rb + g    ) * AST + ks * 8 + t + 4]);
                a[mi][3] = __float_as_uint(Ab[(rb + g + 8) * AST + ks * 8 + t + 4]);
            }
#pragma unroll
            for (int ni = 0; ni < 4; ni++) {
                int cb = wn + ni * 8 + g;
                b[ni][0] = __float_as_uint(Bb[(ks * 8 + t    ) * BST + cb]);
                b[ni][1] = __float_as_uint(Bb[(ks * 8 + t + 4) * BST + cb]);
            }
#pragma unroll
            for (int mi = 0; mi < 4; mi++)
#pragma unroll
                for (int ni = 0; ni < 4; ni++) {
                    asm volatile(
                        "mma.sync.aligned.m16n8k8.row.col.f32.tf32.tf32.f32 "
                        "{%0,%1,%2,%3}, {%4,%5,%6,%7}, {%8,%9}, {%0,%1,%2,%3};\n"
                        : "+f"(acc[mi][ni][0]), "+f"(acc[mi][ni][1]),
                          "+f"(acc[mi][ni][2]), "+f"(acc[mi][ni][3])
                        : "r"(a[mi][0]), "r"(a[mi][1]), "r"(a[mi][2]), "r"(a[mi][3]),
                          "r"(b[ni][0]), "r"(b[ni][1]));
                }
        }
    }

    // fused epilogue: tanh(acc + bias)
#pragma unroll
    for (int mi = 0; mi < 4; mi++) {
        int r0 = row0 + wm + mi * 16 + g;
        int r1 = r0 + 8;
#pragma unroll
        for (int ni = 0; ni < 4; ni++) {
            int cc = col0 + wn + ni * 8 + 2 * t;
            float b0 = bias[cc], b1 = bias[cc + 1];
            if (r0 < M) {
                C[(size_t)r0 * N + cc]     = tanhf(acc[mi][ni][0] + b0);
                C[(size_t)r0 * N + cc + 1] = tanhf(acc[mi][ni][1] + b1);
            }
            if (r1 < M) {
                C[(size_t)r1 * N + cc]     = tanhf(acc[mi][ni][2] + b0);
                C[(size_t)r1 * N + cc + 1] = tanhf(acc[mi][ni][3] + b1);
            }
        }
    }
}

// ---------------- readout ----------------
__global__ void pool_kernel(const float* __restrict__ Y, const int* __restrict__ order) {
    int c = blockIdx.x * blockDim.x + threadIdx.x;   // 0..1023
    int rows = order[0] + 1;
    float s = 0.f;
    for (int r = 0; r < rows; r++) s += Y[(size_t)r * MAXD + c];
    g_pool[c] = s / (float)rows;
}

__global__ void logits_kernel(const float* __restrict__ relW,
                              const float* __restrict__ relB,
                              const int* __restrict__ rel,
                              float* __restrict__ out)
{
    int t = threadIdx.x;   // 64 threads
    float s = relB[t];
    for (int k = 0; k < MAXD; k++) s += g_pool[k] * relW[k * 64 + t];
    __shared__ float lg[64];
    lg[t] = s;
    __syncthreads();
    if (t == 0) {
        int idx[64];
        int cnt = 0;
        for (int i = 0; i < 64; i++)
            if (rel[i] != 0) idx[cnt++] = i;
        for (int k = cnt; k < 64; k++) idx[k] = 0;   // jnp.nonzero pad fill=0
        for (int k = 0; k < 64; k++) out[k] = lg[idx[k]];
    }
}

// ---------------- launch ----------------
extern "C" void kernel_launch(void* const* d_in, const int* in_sizes, int n_in,
                              void* d_out, int out_size)
{
    const float* feat  = (const float*)d_in[0];
    const float* W[4]  = {(const float*)d_in[1], (const float*)d_in[5],
                          (const float*)d_in[9], (const float*)d_in[13]};
    const float* al[4] = {(const float*)d_in[2], (const float*)d_in[6],
                          (const float*)d_in[10], (const float*)d_in[14]};
    const float* ar[4] = {(const float*)d_in[3], (const float*)d_in[7],
                          (const float*)d_in[11], (const float*)d_in[15]};
    const float* bb[4] = {(const float*)d_in[4], (const float*)d_in[8],
                          (const float*)d_in[12], (const float*)d_in[16]};
    const float* relW  = (const float*)d_in[17];
    const float* relB  = (const float*)d_in[18];
    const int*   src   = (const int*)d_in[19];
    const int*   dst   = (const int*)d_in[20];
    const int*   rel   = (const int*)d_in[21];
    const int*   order = (const int*)d_in[22];
    float* out = (float*)d_out;

    float *pA, *pB, *pZ, *pWt;
    cudaGetSymbolAddress((void**)&pA,  g_bufA);
    cudaGetSymbolAddress((void**)&pB,  g_bufB);
    cudaGetSymbolAddress((void**)&pZ,  g_Z);
    cudaGetSymbolAddress((void**)&pWt, g_Wt);

    cudaFuncSetAttribute(gemm_tf32_kernel,
                         cudaFuncAttributeMaxDynamicSharedMemorySize, GEMM_SMEM);

    // CSR (by dst)
    zero_kernel <<<(N_NODES + 255) / 256, 256>>>();
    count_kernel<<<(N_EDGES + 255) / 256, 256>>>(dst);
    scan_kernel <<<1, 1024>>>();
    fill_kernel <<<(N_EDGES + 255) / 256, 256>>>(src, dst);

    const int din_a [4] = {64, 128, 256, 512};
    const int dout_a[4] = {128, 256, 512, 1024};
    const int l2c_a [4] = {0, 1, 2, 3};      // log2(din/64)

    const float* x = feat;
    float* outbufs[4] = {pA, pB, pA, pB};

    for (int l = 0; l < 4; l++) {
        int din = din_a[l], dout = dout_a[l];

        wv_kernel<<<(din * 32 + 255) / 256, 256>>>(W[l], al[l], ar[l], din, dout);
        elr_kernel<<<(N_NODES * 32 + 255) / 256, 256>>>(x, din);
        alpha_kernel<<<(N_NODES * 32 + 255) / 256, 256>>>();

        int warps = N_NODES << l2c_a[l];
        gather_kernel<<<(warps * 32 + 255) / 256, 256>>>(x, pZ, din, l2c_a[l]);

        int wn_elems = din * dout;
        round_kernel<<<(wn_elems + 255) / 256, 256>>>(W[l], pWt, wn_elems);

        float* y = outbufs[l];
        dim3 grid(dout / GBN, (N_NODES + GBM - 1) / GBM);
        gemm_tf32_kernel<<<grid, 256, GEMM_SMEM>>>(pZ, pWt, bb[l], y, N_NODES, din, dout);

        x = y;
    }

    pool_kernel<<<MAXD / 256, 256>>>(pB, order);
    logits_kernel<<<1, 64>>>(relW, relB, rel, out);
}

// round 8
// speedup vs baseline: 1.6080x; 1.0949x over previous
#include <cuda_runtime.h>
#include <cuda_bf16.h>
#include <cmath>

#define N_NODES 20000
#define N_EDGES 320000
#define MAXD    1024

// GEMM tiling constants (fixed for the whole pipeline)
#define GBM 128
#define GBN 128
#define GBK 16
#define A_TILE_F 2304     // 64 lane-slots * 36 floats (32 used + 4 pad)
#define B_TILE_F 2560     // 128 lane-slots * 20 floats (16 used + 4 pad)
#define GEMM_SMEM (3 * (A_TILE_F + B_TILE_F) * 4)   // 58368 bytes

// ---------------- scratch (static __device__, zero-init, no allocs) ----------------
__device__ float g_bufA[(size_t)N_NODES * MAXD];
__device__ float g_bufB[(size_t)N_NODES * MAXD];
// Zp: permuted GEMM-A buffer: [mt(157)][kt(<=32)][lane-slot(64)][36]
__device__ float g_Z  [(size_t)157 * 32 * A_TILE_F];
// Wp: permuted GEMM-B buffer: [kt(<=32)][nt(<=8)][lane-slot(128)][20]
__device__ float g_Wt [(size_t)32 * 8 * B_TILE_F];
__device__ float g_el[N_NODES];
__device__ float g_er[N_NODES];
__device__ float g_wal[512];
__device__ float g_war[512];
__device__ float g_alpha[N_EDGES];
__device__ int   g_rowptr[N_NODES + 1];
__device__ int   g_cnt[N_NODES];
__device__ int   g_fill[N_NODES];
__device__ int   g_csrc[N_EDGES];
__device__ float g_pool[MAXD];

__device__ __forceinline__ unsigned f2tf32(float f) {
    unsigned u;
    asm("cvt.rna.tf32.f32 %0, %1;" : "=r"(u) : "f"(f));
    return u;
}

// ---------------- CSR build ----------------
__global__ void zero_kernel() {
    int i = blockIdx.x * blockDim.x + threadIdx.x;
    if (i < N_NODES) { g_cnt[i] = 0; g_fill[i] = 0; }
}
__global__ void count_kernel(const int* __restrict__ dst) {
    int e = blockIdx.x * blockDim.x + threadIdx.x;
    if (e < N_EDGES) atomicAdd(&g_cnt[dst[e]], 1);
}
__global__ void scan_kernel() {
    __shared__ int sd[1024];
    __shared__ int carry;
    if (threadIdx.x == 0) carry = 0;
    __syncthreads();
    for (int base = 0; base < N_NODES; base += 1024) {
        int i = base + threadIdx.x;
        int v = (i < N_NODES) ? g_cnt[i] : 0;
        sd[threadIdx.x] = v;
        __syncthreads();
        for (int off = 1; off < 1024; off <<= 1) {
            int t = (threadIdx.x >= off) ? sd[threadIdx.x - off] : 0;
            __syncthreads();
            sd[threadIdx.x] += t;
            __syncthreads();
        }
        if (i < N_NODES) g_rowptr[i] = carry + sd[threadIdx.x] - v;
        __syncthreads();
        if (threadIdx.x == 0) carry += sd[1023];
        __syncthreads();
    }
    if (threadIdx.x == 0) g_rowptr[N_NODES] = carry;
}
__global__ void fill_kernel(const int* __restrict__ src, const int* __restrict__ dst) {
    int e = blockIdx.x * blockDim.x + threadIdx.x;
    if (e < N_EDGES) {
        int d = dst[e];
        int p = atomicAdd(&g_fill[d], 1);
        g_csrc[g_rowptr[d] + p] = src[e];
    }
}

// ---------------- projection vectors wal = W@al, war = W@ar ----------------
__global__ void wv_kernel(const float* __restrict__ W,
                          const float* __restrict__ al,
                          const float* __restrict__ ar, int din, int dout)
{
    int g = blockIdx.x * blockDim.x + threadIdx.x;
    int i = g >> 5, lane = g & 31;
    if (i >= din) return;
    const float* row = W + (size_t)i * dout;
    float sl = 0.f, sr = 0.f;
    for (int j = lane; j < dout; j += 32) {
        float w = row[j];
        sl += w * al[j];
        sr += w * ar[j];
    }
#pragma unroll
    for (int o = 16; o > 0; o >>= 1) {
        sl += __shfl_down_sync(0xffffffffu, sl, o);
        sr += __shfl_down_sync(0xffffffffu, sr, o);
    }
    if (lane == 0) { g_wal[i] = sl; g_war[i] = sr; }
}

// ---------------- per-node el / er ----------------
__global__ void elr_kernel(const float* __restrict__ X, int din)
{
    int g = blockIdx.x * blockDim.x + threadIdx.x;
    int node = g >> 5, lane = g & 31;
    if (node >= N_NODES) return;
    const float* row = X + (size_t)node * din;
    float sl = 0.f, sr = 0.f;
    for (int c = lane; c < din; c += 32) {
        float v = row[c];
        sl += v * g_wal[c];
        sr += v * g_war[c];
    }
#pragma unroll
    for (int o = 16; o > 0; o >>= 1) {
        sl += __shfl_down_sync(0xffffffffu, sl, o);
        sr += __shfl_down_sync(0xffffffffu, sr, o);
    }
    if (lane == 0) { g_el[node] = sl; g_er[node] = sr; }
}

// ---------------- normalized edge softmax weights (warp per dst) ----------------
__global__ void alpha_kernel()
{
    int g = blockIdx.x * blockDim.x + threadIdx.x;
    int node = g >> 5, lane = g & 31;
    if (node >= N_NODES) return;
    int beg = g_rowptr[node], end = g_rowptr[node + 1];
    int dg = end - beg;
    if (dg == 0) return;
    float er_n = g_er[node];

    if (dg <= 32) {
        float x = -INFINITY;
        if (lane < dg) {
            x = g_el[g_csrc[beg + lane]] + er_n;
            x = x > 0.f ? x : 0.2f * x;
        }
        float m = x;
#pragma unroll
        for (int o = 16; o > 0; o >>= 1)
            m = fmaxf(m, __shfl_xor_sync(0xffffffffu, m, o));
        float w = (lane < dg) ? __expf(x - m) : 0.f;
        float s = w;
#pragma unroll
        for (int o = 16; o > 0; o >>= 1)
            s += __shfl_xor_sync(0xffffffffu, s, o);
        if (lane < dg) g_alpha[beg + lane] = w / s;
        return;
    }

    float m = -INFINITY;
    for (int i = beg + lane; i < end; i += 32) {
        float x = g_el[g_csrc[i]] + er_n;
        x = x > 0.f ? x : 0.2f * x;
        m = fmaxf(m, x);
    }
#pragma unroll
    for (int o = 16; o > 0; o >>= 1)
        m = fmaxf(m, __shfl_xor_sync(0xffffffffu, m, o));
    float s = 0.f;
    for (int i = beg + lane; i < end; i += 32) {
        float x = g_el[g_csrc[i]] + er_n;
        x = x > 0.f ? x : 0.2f * x;
        float w = __expf(x - m);
        g_alpha[i] = w;
        s += w;
    }
#pragma unroll
    for (int o = 16; o > 0; o >>= 1)
        s += __shfl_xor_sync(0xffffffffu, s, o);
    float inv = 1.f / s;
    for (int i = beg + lane; i < end; i += 32)
        g_alpha[i] *= inv;
}

// ---------------- permuted Z offset: fragment-order layout for GEMM A ----------------
// value (node, c) -> Zp[((mt*nkt + kt)*64 + warp_m*32 + g2*4 + t2)*36 + ks*16 + mi*4 + rh + 2*kh]
__device__ __forceinline__ size_t zp_off(int node, int c, int nkt) {
    int mt = node >> 7, mm = node & 127;
    int wmi = mm >> 6, mr = mm & 63;
    int mi = mr >> 4, rem = mr & 15;
    int g2 = rem & 7, rh = rem >> 3;
    int kt = c >> 4, kk = c & 15;
    int ks = kk >> 3, r = kk & 7;
    int t2 = r & 3, kh = r >> 2;
    return ((size_t)(mt * nkt + kt)) * A_TILE_F
         + (size_t)((wmi * 32 + g2 * 4 + t2) * 36 + ks * 16 + mi * 4 + rh + 2 * kh);
}

// ---------------- weighted gather: warp per (node, 64-channel chunk) ----------------
// writes Z in permuted fragment layout, tf32-rounded
__global__ __launch_bounds__(256) void gather_kernel(
    const float* __restrict__ X, float* __restrict__ Zp, int din, int log2c)
{
    int wg   = (blockIdx.x * blockDim.x + threadIdx.x) >> 5;
    int lane = threadIdx.x & 31;
    int node  = wg >> log2c;
    int chunk = wg & ((1 << log2c) - 1);
    if (node >= N_NODES) return;
    int c0 = chunk * 64 + lane;
    int beg = g_rowptr[node], end = g_rowptr[node + 1];

    const float* Xc = X + c0;
    float acc0 = 0.f, acc1 = 0.f;
    for (int base = beg; base < end; base += 32) {
        int n_e = min(32, end - base);
        int s = 0; float w = 0.f;
        if (lane < n_e) {
            s = g_csrc[base + lane];
            w = g_alpha[base + lane];
        }
#pragma unroll 4
        for (int j = 0; j < n_e; j++) {
            int   sj = __shfl_sync(0xffffffffu, s, j);
            float wj = __shfl_sync(0xffffffffu, w, j);
            const float* row = Xc + (size_t)sj * din;
            acc0 += wj * row[0];
            acc1 += wj * row[32];
        }
    }
    int nkt = din >> 4;
    Zp[zp_off(node, c0,      nkt)] = __uint_as_float(f2tf32(acc0));
    Zp[zp_off(node, c0 + 32, nkt)] = __uint_as_float(f2tf32(acc1));
}

// ---------------- permute W into fragment-order layout (tf32-rounded) ----------------
// value (k, n) -> Wp[((kt*ntn + nt)*128 + wn*32 + g*4 + t)*20 + ks*8 + ni*2 + kh]
__global__ void wperm_kernel(const float* __restrict__ W, float* __restrict__ Wp,
                             int din, int dout)
{
    int i = blockIdx.x * blockDim.x + threadIdx.x;
    if (i >= din * dout) return;
    int k = i / dout, n = i % dout;
    int ntn = dout >> 7;
    int kt = k >> 4, kk = k & 15;
    int ks = kk >> 3, r = kk & 7;
    int t = r & 3, kh = r >> 2;
    int nt = n >> 7, nn = n & 127;
    int wn = nn >> 5, rest = nn & 31;
    int ni = rest >> 3, g = rest & 7;
    size_t off = ((size_t)(kt * ntn + nt)) * B_TILE_F
               + (size_t)((wn * 32 + g * 4 + t) * 20 + ks * 8 + ni * 2 + kh);
    Wp[off] = __uint_as_float(f2tf32(W[i]));
}

// ---------------- tf32 GEMM, fragment-layout smem, 3-stage cp.async ----------------
__device__ __forceinline__ void cp_async16(void* smem_dst, const void* gsrc) {
    unsigned s = (unsigned)__cvta_generic_to_shared(smem_dst);
    asm volatile("cp.async.cg.shared.global [%0], [%1], 16;\n" :: "r"(s), "l"(gsrc));
}

__global__ __launch_bounds__(256, 2) void gemm_tf32_kernel(
    const float* __restrict__ Ap, const float* __restrict__ Bp,
    const float* __restrict__ bias, float* __restrict__ C,
    int M, int K, int N)
{
    extern __shared__ float smbuf[];
    float* Asm = smbuf;                  // [3][A_TILE_F]
    float* Bsm = smbuf + 3 * A_TILE_F;   // [3][B_TILE_F]

    int tid  = threadIdx.x;
    int lane = tid & 31;
    int warp = tid >> 5;
    int wm = (warp >> 2) * 64;
    int wn = (warp & 3) * 32;
    int g = lane >> 2;
    int t = lane & 3;

    int nkt = K >> 4;
    int ntn = N >> 7;
    int mt = blockIdx.y;
    int nt = blockIdx.x;
    int row0 = mt * GBM;
    int col0 = nt * GBN;

    int aBase = ((warp >> 2) * 32 + lane) * 36;   // per-lane A slot
    int bBase = ((warp & 3) * 32 + lane) * 20;    // per-lane B slot

    float acc[4][4][4];
#pragma unroll
    for (int mi = 0; mi < 4; mi++)
#pragma unroll
        for (int ni = 0; ni < 4; ni++)
#pragma unroll
            for (int r = 0; r < 4; r++) acc[mi][ni][r] = 0.f;

    auto load_stage = [&](int it) {
        int buf = it % 3;
        float* Ab = Asm + buf * A_TILE_F;
        float* Bb = Bsm + buf * B_TILE_F;
        const float* Ag = Ap + ((size_t)(mt * nkt + it)) * A_TILE_F;
        const float* Bg = Bp + ((size_t)(it * ntn + nt)) * B_TILE_F;
#pragma unroll
        for (int i = 0; i < 3; i++) {
            int c = tid + i * 256;
            if (c < A_TILE_F / 4) cp_async16(Ab + c * 4, Ag + c * 4);
        }
#pragma unroll
        for (int i = 0; i < 3; i++) {
            int c = tid + i * 256;
            if (c < B_TILE_F / 4) cp_async16(Bb + c * 4, Bg + c * 4);
        }
        asm volatile("cp.async.commit_group;\n" ::: "memory");
    };

    load_stage(0);
    load_stage(1);

    int nk = nkt;
    for (int it = 0; it < nk; it++) {
        int cur = it % 3;
        if (it + 1 < nk) {
            asm volatile("cp.async.wait_group 1;\n" ::: "memory");
        } else {
            asm volatile("cp.async.wait_group 0;\n" ::: "memory");
        }
        __syncthreads();
        if (it + 2 < nk) load_stage(it + 2);

        const float* Ab = Asm + cur * A_TILE_F;
        const float* Bb = Bsm + cur * B_TILE_F;
#pragma unroll
        for (int ks = 0; ks < 2; ks++) {
            // A fragments: one LDS.128 per (mi, ks)
            float4 av[4];
#pragma unroll
            for (int mi = 0; mi < 4; mi++)
                av[mi] = *(const float4*)(Ab + aBase + ks * 16 + mi * 4);
            // B fragments: two LDS.128 per ks
            float4 bv0 = *(const float4*)(Bb + bBase + ks * 8);
            float4 bv1 = *(const float4*)(Bb + bBase + ks * 8 + 4);
            unsigned b00 = __float_as_uint(bv0.x), b01 = __float_as_uint(bv0.y);
            unsigned b10 = __float_as_uint(bv0.z), b11 = __float_as_uint(bv0.w);
            unsigned b20 = __float_as_uint(bv1.x), b21 = __float_as_uint(bv1.y);
            unsigned b30 = __float_as_uint(bv1.z), b31 = __float_as_uint(bv1.w);
            unsigned bB[4][2] = {{b00,b01},{b10,b11},{b20,b21},{b30,b31}};
#pragma unroll
            for (int mi = 0; mi < 4; mi++) {
                unsigned a0 = __float_as_uint(av[mi].x);
                unsigned a1 = __float_as_uint(av[mi].y);
                unsigned a2 = __float_as_uint(av[mi].z);
                unsigned a3 = __float_as_uint(av[mi].w);
#pragma unroll
                for (int ni = 0; ni < 4; ni++) {
                    asm volatile(
                        "mma.sync.aligned.m16n8k8.row.col.f32.tf32.tf32.f32 "
                        "{%0,%1,%2,%3}, {%4,%5,%6,%7}, {%8,%9}, {%0,%1,%2,%3};\n"
                        : "+f"(acc[mi][ni][0]), "+f"(acc[mi][ni][1]),
                          "+f"(acc[mi][ni][2]), "+f"(acc[mi][ni][3])
                        : "r"(a0), "r"(a1), "r"(a2), "r"(a3),
                          "r"(bB[ni][0]), "r"(bB[ni][1]));
                }
            }
        }
    }

    // fused epilogue: tanh(acc + bias)
#pragma unroll
    for (int mi = 0; mi < 4; mi++) {
        int r0 = row0 + wm + mi * 16 + g;
        int r1 = r0 + 8;
#pragma unroll
        for (int ni = 0; ni < 4; ni++) {
            int cc = col0 + wn + ni * 8 + 2 * t;
            float b0 = bias[cc], b1 = bias[cc + 1];
            if (r0 < M) {
                C[(size_t)r0 * N + cc]     = tanhf(acc[mi][ni][0] + b0);
                C[(size_t)r0 * N + cc + 1] = tanhf(acc[mi][ni][1] + b1);
            }
            if (r1 < M) {
                C[(size_t)r1 * N + cc]     = tanhf(acc[mi][ni][2] + b0);
                C[(size_t)r1 * N + cc + 1] = tanhf(acc[mi][ni][3] + b1);
            }
        }
    }
}

// ---------------- readout ----------------
__global__ void pool_kernel(const float* __restrict__ Y, const int* __restrict__ order) {
    int c = blockIdx.x * blockDim.x + threadIdx.x;   // 0..1023
    int rows = order[0] + 1;
    float s = 0.f;
    for (int r = 0; r < rows; r++) s += Y[(size_t)r * MAXD + c];
    g_pool[c] = s / (float)rows;
}

__global__ void logits_kernel(const float* __restrict__ relW,
                              const float* __restrict__ relB,
                              const int* __restrict__ rel,
                              float* __restrict__ out)
{
    int t = threadIdx.x;   // 64 threads
    float s = relB[t];
    for (int k = 0; k < MAXD; k++) s += g_pool[k] * relW[k * 64 + t];
    __shared__ float lg[64];
    lg[t] = s;
    __syncthreads();
    if (t == 0) {
        int idx[64];
        int cnt = 0;
        for (int i = 0; i < 64; i++)
            if (rel[i] != 0) idx[cnt++] = i;
        for (int k = cnt; k < 64; k++) idx[k] = 0;   // jnp.nonzero pad fill=0
        for (int k = 0; k < 64; k++) out[k] = lg[idx[k]];
    }
}

// ---------------- launch ----------------
extern "C" void kernel_launch(void* const* d_in, const int* in_sizes, int n_in,
                              void* d_out, int out_size)
{
    const float* feat  = (const float*)d_in[0];
    const float* W[4]  = {(const float*)d_in[1], (const float*)d_in[5],
                          (const float*)d_in[9], (const float*)d_in[13]};
    const float* al[4] = {(const float*)d_in[2], (const float*)d_in[6],
                          (const float*)d_in[10], (const float*)d_in[14]};
    const float* ar[4] = {(const float*)d_in[3], (const float*)d_in[7],
                          (const float*)d_in[11], (const float*)d_in[15]};
    const float* bb[4] = {(const float*)d_in[4], (const float*)d_in[8],
                          (const float*)d_in[12], (const float*)d_in[16]};
    const float* relW  = (const float*)d_in[17];
    const float* relB  = (const float*)d_in[18];
    const int*   src   = (const int*)d_in[19];
    const int*   dst   = (const int*)d_in[20];
    const int*   rel   = (const int*)d_in[21];
    const int*   order = (const int*)d_in[22];
    float* out = (float*)d_out;

    float *pA, *pB, *pZ, *pWt;
    cudaGetSymbolAddress((void**)&pA,  g_bufA);
    cudaGetSymbolAddress((void**)&pB,  g_bufB);
    cudaGetSymbolAddress((void**)&pZ,  g_Z);
    cudaGetSymbolAddress((void**)&pWt, g_Wt);

    cudaFuncSetAttribute(gemm_tf32_kernel,
                         cudaFuncAttributeMaxDynamicSharedMemorySize, GEMM_SMEM);

    // CSR (by dst)
    zero_kernel <<<(N_NODES + 255) / 256, 256>>>();
    count_kernel<<<(N_EDGES + 255) / 256, 256>>>(dst);
    scan_kernel <<<1, 1024>>>();
    fill_kernel <<<(N_EDGES + 255) / 256, 256>>>(src, dst);

    const int din_a [4] = {64, 128, 256, 512};
    const int dout_a[4] = {128, 256, 512, 1024};
    const int l2c_a [4] = {0, 1, 2, 3};      // log2(din/64)

    const float* x = feat;
    float* outbufs[4] = {pA, pB, pA, pB};

    for (int l = 0; l < 4; l++) {
        int din = din_a[l], dout = dout_a[l];

        wv_kernel<<<(din * 32 + 255) / 256, 256>>>(W[l], al[l], ar[l], din, dout);
        elr_kernel<<<(N_NODES * 32 + 255) / 256, 256>>>(x, din);
        alpha_kernel<<<(N_NODES * 32 + 255) / 256, 256>>>();

        int warps = N_NODES << l2c_a[l];
        gather_kernel<<<(warps * 32 + 255) / 256, 256>>>(x, pZ, din, l2c_a[l]);

        int wn_elems = din * dout;
        wperm_kernel<<<(wn_elems + 255) / 256, 256>>>(W[l], pWt, din, dout);

        float* y = outbufs[l];
        dim3 grid(dout / GBN, (N_NODES + GBM - 1) / GBM);
        gemm_tf32_kernel<<<grid, 256, GEMM_SMEM>>>(pZ, pWt, bb[l], y, N_NODES, din, dout);

        x = y;
    }

    pool_kernel<<<MAXD / 256, 256>>>(pB, order);
    logits_kernel<<<1, 64>>>(relW, relB, rel, out);
}

// round 9
// speedup vs baseline: 1.7814x; 1.1078x over previous
#include <cuda_runtime.h>
#include <cuda_bf16.h>
#include <cmath>

#define N_NODES 20000
#define N_EDGES 320000
#define MAXD    1024

// GEMM tiling constants
#define GBM 128
#define GBN 128
#define GBK 16
#define A_TILE_F 2304     // 64 lane-slots * 36 floats
#define B_TILE_F 2560     // 128 lane-slots * 20 floats
#define GEMM_SMEM (3 * (A_TILE_F + B_TILE_F) * 4)   // 58368 bytes

// fused prep kernel block ranges
#define FILL_B   1250
#define WV_B     120      // din/8 per layer: 8+16+32+64
#define WPERM_B  2720     // din*dout/256 per layer: 32+128+512+2048
#define PREP_B   (FILL_B + WV_B + WPERM_B)

// ---------------- scratch (static __device__, zero-init, no allocs) ----------------
__device__ float g_bufA[(size_t)N_NODES * MAXD];
__device__ float g_bufB[(size_t)N_NODES * MAXD];
__device__ float g_Z  [(size_t)157 * 32 * A_TILE_F];          // permuted GEMM-A
__device__ float g_Wp [(size_t)340 * B_TILE_F];               // permuted GEMM-B, 4 layers packed
__device__ float g_el[N_NODES];
__device__ float g_er[N_NODES];
__device__ float g_wal[4][512];
__device__ float g_war[4][512];
__device__ float g_alpha[N_EDGES];
__device__ int   g_rowptr[N_NODES + 1];
__device__ int   g_cnt[N_NODES];
__device__ int   g_fill[N_NODES];
__device__ int   g_csrc[N_EDGES];
__device__ float g_pool[MAXD];

__device__ __forceinline__ unsigned f2tf32(float f) {
    unsigned u;
    asm("cvt.rna.tf32.f32 %0, %1;" : "=r"(u) : "f"(f));
    return u;
}

__constant__ int c_din[4]  = {64, 128, 256, 512};
__constant__ int c_dout[4] = {128, 256, 512, 1024};
__constant__ int c_wpoff[4] = {0, 4, 20, 84};    // Wp tile offsets (tiles of B_TILE_F)

// ---------------- CSR build ----------------
__global__ void zero_kernel() {
    int i = blockIdx.x * blockDim.x + threadIdx.x;
    if (i < N_NODES) { g_cnt[i] = 0; g_fill[i] = 0; }
    if (i < MAXD) g_pool[i] = 0.f;
}
__global__ void count_kernel(const int* __restrict__ dst) {
    int e = blockIdx.x * blockDim.x + threadIdx.x;
    if (e < N_EDGES) atomicAdd(&g_cnt[dst[e]], 1);
}
// 1 block, 1024 threads, 20 nodes each: sequential local scan + one block scan
__global__ void scan_kernel() {
    __shared__ int ssum[1024];
    int tid = threadIdx.x;
    int b = tid * 20;
    int tot = 0;
    for (int i = 0; i < 20; i++) {
        int idx = b + i;
        if (idx < N_NODES) {
            g_rowptr[idx] = tot;
            tot += g_cnt[idx];
        }
    }
    ssum[tid] = tot;
    __syncthreads();
    for (int off = 1; off < 1024; off <<= 1) {
        int t = (tid >= off) ? ssum[tid - off] : 0;
        __syncthreads();
        ssum[tid] += t;
        __syncthreads();
    }
    int base = (tid > 0) ? ssum[tid - 1] : 0;
    if (base != 0)
        for (int i = 0; i < 20; i++) {
            int idx = b + i;
            if (idx < N_NODES) g_rowptr[idx] += base;
        }
    if (tid == 1023) g_rowptr[N_NODES] = ssum[1023];
}

// ---------------- fused prep: fill CSR + wv(4 layers) + wperm(4 layers) ----------------
__global__ __launch_bounds__(256) void prep_kernel(
    const int* __restrict__ src, const int* __restrict__ dst,
    const float* __restrict__ W0, const float* __restrict__ W1,
    const float* __restrict__ W2, const float* __restrict__ W3,
    const float* __restrict__ al0, const float* __restrict__ al1,
    const float* __restrict__ al2, const float* __restrict__ al3,
    const float* __restrict__ ar0, const float* __restrict__ ar1,
    const float* __restrict__ ar2, const float* __restrict__ ar3)
{
    const float* Ws[4]  = {W0, W1, W2, W3};
    const float* als[4] = {al0, al1, al2, al3};
    const float* ars[4] = {ar0, ar1, ar2, ar3};
    int bid = blockIdx.x;

    if (bid < FILL_B) {
        int e = bid * 256 + threadIdx.x;
        if (e < N_EDGES) {
            int d = dst[e];
            int p = atomicAdd(&g_fill[d], 1);
            g_csrc[g_rowptr[d] + p] = src[e];
        }
        return;
    }
    bid -= FILL_B;
    if (bid < WV_B) {
        // wv: warp per din-row; layer by cumulative din/8 blocks {8,16,32,64}
        int l, b0;
        if      (bid < 8)  { l = 0; b0 = 0; }
        else if (bid < 24) { l = 1; b0 = 8; }
        else if (bid < 56) { l = 2; b0 = 24; }
        else               { l = 3; b0 = 56; }
        int din = c_din[l], dout = c_dout[l];
        int wid = (bid - b0) * 8 + (threadIdx.x >> 5);
        int lane = threadIdx.x & 31;
        if (wid >= din) return;
        const float* row = Ws[l] + (size_t)wid * dout;
        const float* al = als[l];
        const float* ar = ars[l];
        float sl = 0.f, sr = 0.f;
        for (int j = lane; j < dout; j += 32) {
            float w = row[j];
            sl += w * al[j];
            sr += w * ar[j];
        }
#pragma unroll
        for (int o = 16; o > 0; o >>= 1) {
            sl += __shfl_down_sync(0xffffffffu, sl, o);
            sr += __shfl_down_sync(0xffffffffu, sr, o);
        }
        if (lane == 0) { g_wal[l][wid] = sl; g_war[l][wid] = sr; }
        return;
    }
    bid -= WV_B;
    {
        // wperm: element per thread; layer by cumulative elems/256 blocks {32,128,512,2048}
        int l, b0;
        if      (bid < 32)  { l = 0; b0 = 0; }
        else if (bid < 160) { l = 1; b0 = 32; }
        else if (bid < 672) { l = 2; b0 = 160; }
        else                { l = 3; b0 = 672; }
        int din = c_din[l], dout = c_dout[l];
        int i = (bid - b0) * 256 + threadIdx.x;
        if (i >= din * dout) return;
        int k = i / dout, n = i % dout;
        int ntn = dout >> 7;
        int kt = k >> 4, kk = k & 15;
        int ks = kk >> 3, r = kk & 7;
        int t = r & 3, kh = r >> 2;
        int nt = n >> 7, nn = n & 127;
        int wn = nn >> 5, rest = nn & 31;
        int ni = rest >> 3, g = rest & 7;
        size_t off = ((size_t)(c_wpoff[l] + kt * ntn + nt)) * B_TILE_F
                   + (size_t)((wn * 32 + g * 4 + t) * 20 + ks * 8 + ni * 2 + kh);
        g_Wp[off] = __uint_as_float(f2tf32(Ws[l][i]));
    }
}

// ---------------- per-node el / er (float4 vectorized) ----------------
__global__ void elr_kernel(const float* __restrict__ X, int din, int l)
{
    int g = blockIdx.x * blockDim.x + threadIdx.x;
    int node = g >> 5, lane = g & 31;
    if (node >= N_NODES) return;
    const float4* row = (const float4*)(X + (size_t)node * din);
    const float4* wl = (const float4*)g_wal[l];
    const float4* wr = (const float4*)g_war[l];
    int nq = din >> 2;
    float sl = 0.f, sr = 0.f;
    for (int c = lane; c < nq; c += 32) {
        float4 v = row[c];
        float4 a = wl[c];
        float4 b = wr[c];
        sl += v.x * a.x + v.y * a.y + v.z * a.z + v.w * a.w;
        sr += v.x * b.x + v.y * b.y + v.z * b.z + v.w * b.w;
    }
#pragma unroll
    for (int o = 16; o > 0; o >>= 1) {
        sl += __shfl_down_sync(0xffffffffu, sl, o);
        sr += __shfl_down_sync(0xffffffffu, sr, o);
    }
    if (lane == 0) { g_el[node] = sl; g_er[node] = sr; }
}

// ---------------- normalized edge softmax weights (warp per dst) ----------------
__global__ void alpha_kernel()
{
    int g = blockIdx.x * blockDim.x + threadIdx.x;
    int node = g >> 5, lane = g & 31;
    if (node >= N_NODES) return;
    int beg = g_rowptr[node], end = g_rowptr[node + 1];
    int dg = end - beg;
    if (dg == 0) return;
    float er_n = g_er[node];

    if (dg <= 32) {
        float x = -INFINITY;
        if (lane < dg) {
            x = g_el[g_csrc[beg + lane]] + er_n;
            x = x > 0.f ? x : 0.2f * x;
        }
        float m = x;
#pragma unroll
        for (int o = 16; o > 0; o >>= 1)
            m = fmaxf(m, __shfl_xor_sync(0xffffffffu, m, o));
        float w = (lane < dg) ? __expf(x - m) : 0.f;
        float s = w;
#pragma unroll
        for (int o = 16; o > 0; o >>= 1)
            s += __shfl_xor_sync(0xffffffffu, s, o);
        if (lane < dg) g_alpha[beg + lane] = w / s;
        return;
    }

    float m = -INFINITY;
    for (int i = beg + lane; i < end; i += 32) {
        float x = g_el[g_csrc[i]] + er_n;
        x = x > 0.f ? x : 0.2f * x;
        m = fmaxf(m, x);
    }
#pragma unroll
    for (int o = 16; o > 0; o >>= 1)
        m = fmaxf(m, __shfl_xor_sync(0xffffffffu, m, o));
    float s = 0.f;
    for (int i = beg + lane; i < end; i += 32) {
        float x = g_el[g_csrc[i]] + er_n;
        x = x > 0.f ? x : 0.2f * x;
        float w = __expf(x - m);
        g_alpha[i] = w;
        s += w;
    }
#pragma unroll
    for (int o = 16; o > 0; o >>= 1)
        s += __shfl_xor_sync(0xffffffffu, s, o);
    float inv = 1.f / s;
    for (int i = beg + lane; i < end; i += 32)
        g_alpha[i] *= inv;
}

// ---------------- permuted Z offset (fragment-order GEMM A layout) ----------------
__device__ __forceinline__ size_t zp_off(int node, int c, int nkt) {
    int mt = node >> 7, mm = node & 127;
    int wmi = mm >> 6, mr = mm & 63;
    int mi = mr >> 4, rem = mr & 15;
    int g2 = rem & 7, rh = rem >> 3;
    int kt = c >> 4, kk = c & 15;
    int ks = kk >> 3, r = kk & 7;
    int t2 = r & 3, kh = r >> 2;
    return ((size_t)(mt * nkt + kt)) * A_TILE_F
         + (size_t)((wmi * 32 + g2 * 4 + t2) * 36 + ks * 16 + mi * 4 + rh + 2 * kh);
}

// ---------------- weighted gather -> permuted Z ----------------
__global__ __launch_bounds__(256) void gather_kernel(
    const float* __restrict__ X, float* __restrict__ Zp, int din, int log2c)
{
    int wg   = (blockIdx.x * blockDim.x + threadIdx.x) >> 5;
    int lane = threadIdx.x & 31;
    int node  = wg >> log2c;
    int chunk = wg & ((1 << log2c) - 1);
    if (node >= N_NODES) return;
    int c0 = chunk * 64 + lane;
    int beg = g_rowptr[node], end = g_rowptr[node + 1];

    const float* Xc = X + c0;
    float acc0 = 0.f, acc1 = 0.f;
    for (int base = beg; base < end; base += 32) {
        int n_e = min(32, end - base);
        int s = 0; float w = 0.f;
        if (lane < n_e) {
            s = g_csrc[base + lane];
            w = g_alpha[base + lane];
        }
#pragma unroll 4
        for (int j = 0; j < n_e; j++) {
            int   sj = __shfl_sync(0xffffffffu, s, j);
            float wj = __shfl_sync(0xffffffffu, w, j);
            const float* row = Xc + (size_t)sj * din;
            acc0 += wj * row[0];
            acc1 += wj * row[32];
        }
    }
    int nkt = din >> 4;
    Zp[zp_off(node, c0,      nkt)] = __uint_as_float(f2tf32(acc0));
    Zp[zp_off(node, c0 + 32, nkt)] = __uint_as_float(f2tf32(acc1));
}

// ---------------- tf32 GEMM, fragment-layout smem, 3-stage cp.async ----------------
__device__ __forceinline__ void cp_async16(void* smem_dst, const void* gsrc) {
    unsigned s = (unsigned)__cvta_generic_to_shared(smem_dst);
    asm volatile("cp.async.cg.shared.global [%0], [%1], 16;\n" :: "r"(s), "l"(gsrc));
}

__global__ __launch_bounds__(256, 2) void gemm_tf32_kernel(
    const float* __restrict__ Ap, const float* __restrict__ Bp,
    const float* __restrict__ bias, float* __restrict__ C,
    int M, int K, int N)
{
    extern __shared__ float smbuf[];
    float* Asm = smbuf;
    float* Bsm = smbuf + 3 * A_TILE_F;

    int tid  = threadIdx.x;
    int lane = tid & 31;
    int warp = tid >> 5;
    int wm = (warp >> 2) * 64;
    int wn = (warp & 3) * 32;
    int g = lane >> 2;
    int t = lane & 3;

    int nkt = K >> 4;
    int ntn = N >> 7;
    int mt = blockIdx.y;
    int nt = blockIdx.x;
    int row0 = mt * GBM;
    int col0 = nt * GBN;

    int aBase = ((warp >> 2) * 32 + lane) * 36;
    int bBase = ((warp & 3) * 32 + lane) * 20;

    float acc[4][4][4];
#pragma unroll
    for (int mi = 0; mi < 4; mi++)
#pragma unroll
        for (int ni = 0; ni < 4; ni++)
#pragma unroll
            for (int r = 0; r < 4; r++) acc[mi][ni][r] = 0.f;

    auto load_stage = [&](int it) {
        int buf = it % 3;
        float* Ab = Asm + buf * A_TILE_F;
        float* Bb = Bsm + buf * B_TILE_F;
        const float* Ag = Ap + ((size_t)(mt * nkt + it)) * A_TILE_F;
        const float* Bg = Bp + ((size_t)(it * ntn + nt)) * B_TILE_F;
#pragma unroll
        for (int i = 0; i < 3; i++) {
            int c = tid + i * 256;
            if (c < A_TILE_F / 4) cp_async16(Ab + c * 4, Ag + c * 4);
        }
#pragma unroll
        for (int i = 0; i < 3; i++) {
            int c = tid + i * 256;
            if (c < B_TILE_F / 4) cp_async16(Bb + c * 4, Bg + c * 4);
        }
        asm volatile("cp.async.commit_group;\n" ::: "memory");
    };

    load_stage(0);
    load_stage(1);

    int nk = nkt;
    for (int it = 0; it < nk; it++) {
        int cur = it % 3;
        if (it + 1 < nk) {
            asm volatile("cp.async.wait_group 1;\n" ::: "memory");
        } else {
            asm volatile("cp.async.wait_group 0;\n" ::: "memory");
        }
        __syncthreads();
        if (it + 2 < nk) load_stage(it + 2);

        const float* Ab = Asm + cur * A_TILE_F;
        const float* Bb = Bsm + cur * B_TILE_F;
#pragma unroll
        for (int ks = 0; ks < 2; ks++) {
            float4 av[4];
#pragma unroll
            for (int mi = 0; mi < 4; mi++)
                av[mi] = *(const float4*)(Ab + aBase + ks * 16 + mi * 4);
            float4 bv0 = *(const float4*)(Bb + bBase + ks * 8);
            float4 bv1 = *(const float4*)(Bb + bBase + ks * 8 + 4);
            unsigned bB[4][2] = {
                {__float_as_uint(bv0.x), __float_as_uint(bv0.y)},
                {__float_as_uint(bv0.z), __float_as_uint(bv0.w)},
                {__float_as_uint(bv1.x), __float_as_uint(bv1.y)},
                {__float_as_uint(bv1.z), __float_as_uint(bv1.w)}};
#pragma unroll
            for (int mi = 0; mi < 4; mi++) {
                unsigned a0 = __float_as_uint(av[mi].x);
                unsigned a1 = __float_as_uint(av[mi].y);
                unsigned a2 = __float_as_uint(av[mi].z);
                unsigned a3 = __float_as_uint(av[mi].w);
#pragma unroll
                for (int ni = 0; ni < 4; ni++) {
                    asm volatile(
                        "mma.sync.aligned.m16n8k8.row.col.f32.tf32.tf32.f32 "
                        "{%0,%1,%2,%3}, {%4,%5,%6,%7}, {%8,%9}, {%0,%1,%2,%3};\n"
                        : "+f"(acc[mi][ni][0]), "+f"(acc[mi][ni][1]),
                          "+f"(acc[mi][ni][2]), "+f"(acc[mi][ni][3])
                        : "r"(a0), "r"(a1), "r"(a2), "r"(a3),
                          "r"(bB[ni][0]), "r"(bB[ni][1]));
                }
            }
        }
    }

#pragma unroll
    for (int mi = 0; mi < 4; mi++) {
        int r0 = row0 + wm + mi * 16 + g;
        int r1 = r0 + 8;
#pragma unroll
        for (int ni = 0; ni < 4; ni++) {
            int cc = col0 + wn + ni * 8 + 2 * t;
            float b0 = bias[cc], b1 = bias[cc + 1];
            if (r0 < M) {
                C[(size_t)r0 * N + cc]     = tanhf(acc[mi][ni][0] + b0);
                C[(size_t)r0 * N + cc + 1] = tanhf(acc[mi][ni][1] + b1);
            }
            if (r1 < M) {
                C[(size_t)r1 * N + cc]     = tanhf(acc[mi][ni][2] + b0);
                C[(size_t)r1 * N + cc + 1] = tanhf(acc[mi][ni][3] + b1);
            }
        }
    }
}

// ---------------- readout ----------------
// grid (MAXD/256, 32): block sums rows r = blockIdx.y, y+32, ... then atomicAdd
__global__ void pool_kernel(const float* __restrict__ Y, const int* __restrict__ order) {
    int c = blockIdx.x * blockDim.x + threadIdx.x;
    int rows = order[0] + 1;
    float s = 0.f;
    for (int r = blockIdx.y; r < rows; r += 32)
        s += Y[(size_t)r * MAXD + c];
    atomicAdd(&g_pool[c], s);
}

__global__ void logits_kernel(const float* __restrict__ relW,
                              const float* __restrict__ relB,
                              const int* __restrict__ rel,
                              const int* __restrict__ order,
                              float* __restrict__ out)
{
    int t = threadIdx.x;   // 64 threads
    float inv = 1.f / (float)(order[0] + 1);
    float s = relB[t];
    for (int k = 0; k < MAXD; k++) s += (g_pool[k] * inv) * relW[k * 64 + t];
    __shared__ float lg[64];
    lg[t] = s;
    __syncthreads();
    if (t == 0) {
        int idx[64];
        int cnt = 0;
        for (int i = 0; i < 64; i++)
            if (rel[i] != 0) idx[cnt++] = i;
        for (int k = cnt; k < 64; k++) idx[k] = 0;   // jnp.nonzero pad fill=0
        for (int k = 0; k < 64; k++) out[k] = lg[idx[k]];
    }
}

// ---------------- launch ----------------
extern "C" void kernel_launch(void* const* d_in, const int* in_sizes, int n_in,
                              void* d_out, int out_size)
{
    const float* feat  = (const float*)d_in[0];
    const float* W[4]  = {(const float*)d_in[1], (const float*)d_in[5],
                          (const float*)d_in[9], (const float*)d_in[13]};
    const float* al[4] = {(const float*)d_in[2], (const float*)d_in[6],
                          (const float*)d_in[10], (const float*)d_in[14]};
    const float* ar[4] = {(const float*)d_in[3], (const float*)d_in[7],
                          (const float*)d_in[11], (const float*)d_in[15]};
    const float* bb[4] = {(const float*)d_in[4], (const float*)d_in[8],
                          (const float*)d_in[12], (const float*)d_in[16]};
    const float* relW  = (const float*)d_in[17];
    const float* relB  = (const float*)d_in[18];
    const int*   src   = (const int*)d_in[19];
    const int*   dst   = (const int*)d_in[20];
    const int*   rel   = (const int*)d_in[21];
    const int*   order = (const int*)d_in[22];
    float* out = (float*)d_out;

    float *pA, *pB, *pZ, *pWp;
    cudaGetSymbolAddress((void**)&pA,  g_bufA);
    cudaGetSymbolAddress((void**)&pB,  g_bufB);
    cudaGetSymbolAddress((void**)&pZ,  g_Z);
    cudaGetSymbolAddress((void**)&pWp, g_Wp);

    cudaFuncSetAttribute(gemm_tf32_kernel,
                         cudaFuncAttributeMaxDynamicSharedMemorySize, GEMM_SMEM);

    // CSR + W-prep (wv/wperm hidden behind fill in one fused launch)
    zero_kernel <<<(N_NODES + 255) / 256, 256>>>();
    count_kernel<<<(N_EDGES + 255) / 256, 256>>>(dst);
    scan_kernel <<<1, 1024>>>();
    prep_kernel <<<PREP_B, 256>>>(src, dst,
                                  W[0], W[1], W[2], W[3],
                                  al[0], al[1], al[2], al[3],
                                  ar[0], ar[1], ar[2], ar[3]);

    const int din_a [4] = {64, 128, 256, 512};
    const int dout_a[4] = {128, 256, 512, 1024};
    const int l2c_a [4] = {0, 1, 2, 3};
    const int wpoff [4] = {0, 4, 20, 84};

    const float* x = feat;
    float* outbufs[4] = {pA, pB, pA, pB};

    for (int l = 0; l < 4; l++) {
        int din = din_a[l], dout = dout_a[l];

        elr_kernel<<<(N_NODES * 32 + 255) / 256, 256>>>(x, din, l);
        alpha_kernel<<<(N_NODES * 32 + 255) / 256, 256>>>();

        int warps = N_NODES << l2c_a[l];
        gather_kernel<<<(warps * 32 + 255) / 256, 256>>>(x, pZ, din, l2c_a[l]);

        float* y = outbufs[l];
        dim3 grid(dout / GBN, (N_NODES + GBM - 1) / GBM);
        gemm_tf32_kernel<<<grid, 256, GEMM_SMEM>>>(
            pZ, pWp + (size_t)wpoff[l] * B_TILE_F, bb[l], y, N_NODES, din, dout);

        x = y;
    }

    dim3 pg(MAXD / 256, 32);
    pool_kernel<<<pg, 256>>>(pB, order);
    logits_kernel<<<1, 64>>>(relW, relB, rel, order, out);
}